// round 15
// baseline (speedup 1.0000x reference)
#include <cuda_runtime.h>
#include <cuda_bf16.h>
#include <cuda_fp16.h>
#include <mma.h>
#include <cstdint>

using namespace nvcuda;

// Problem constants (fixed by the dataset)
#define MAXN 50000
#define MAXE 400000
#define HD 256          // H * D
#define D_DIM 128
#define NEG_SLOPE 0.2f

// ---------------- scratch (no allocations allowed) ----------------
__device__ __half g_xlh[(size_t)MAXN * HD];     // source projection, fp16
__device__ __half g_xrh[(size_t)MAXN * HD];     // target projection, fp16
__device__ float  g_numer[(size_t)MAXN * HD];   // weighted sums (fp32 accumulate)
__device__ float  g_denom[(size_t)MAXN * 2];    // sum of exp(score) per node/head
__device__ __half g_xh[(size_t)MAXN * D_DIM];   // x in fp16
__device__ __half g_wh[3 * HD * D_DIM];         // Wl, Wr, Wo in fp16

__device__ __forceinline__ void red_add_v4(float* p, float a, float b, float c, float d) {
    asm volatile("red.global.add.v4.f32 [%0], {%1,%2,%3,%4};"
                 :: "l"(p), "f"(a), "f"(b), "f"(c), "f"(d) : "memory");
}
__device__ __forceinline__ uint4 f32x8_to_h8(float4 a, float4 b) {
    __half2 h0 = __floats2half2_rn(a.x, a.y);
    __half2 h1 = __floats2half2_rn(a.z, a.w);
    __half2 h2 = __floats2half2_rn(b.x, b.y);
    __half2 h3 = __floats2half2_rn(b.z, b.w);
    uint4 u;
    u.x = *(uint32_t*)&h0; u.y = *(uint32_t*)&h1;
    u.z = *(uint32_t*)&h2; u.w = *(uint32_t*)&h3;
    return u;
}
__device__ __forceinline__ void h8_to_f8(uint4 u, float* f) {
    float2 t;
    t = __half22float2(*(__half2*)&u.x); f[0] = t.x; f[1] = t.y;
    t = __half22float2(*(__half2*)&u.y); f[2] = t.x; f[3] = t.y;
    t = __half22float2(*(__half2*)&u.z); f[4] = t.x; f[5] = t.y;
    t = __half22float2(*(__half2*)&u.w); f[6] = t.x; f[7] = t.y;
}

// ---------------- init: zero numer/denom + convert x, Wl, Wr, Wo to fp16 ----------------
__global__ void init_kernel(const float* __restrict__ x,
                            const float* __restrict__ Wl,
                            const float* __restrict__ Wr,
                            const float* __restrict__ Wo, int n_nodes) {
    int i = blockIdx.x * blockDim.x + threadIdx.x;
    int t0 = n_nodes * 64;
    int t1 = t0 + n_nodes * 16;
    if (i < t0) {
        ((float4*)g_numer)[i] = make_float4(0.f, 0.f, 0.f, 0.f);
    } else if (i < t1) {
        int j = i - t0;                       // 8-float chunk of x
        const float4* src = (const float4*)x + (size_t)j * 2;
        ((uint4*)g_xh)[j] = f32x8_to_h8(src[0], src[1]);
    } else if (i < t1 + 12288) {
        int j = i - t1;                       // 8-float chunk; 4096 chunks per matrix
        const float* src = (j < 4096) ? Wl : (j < 8192) ? Wr : Wo;
        int jj = j & 4095;
        const float4* s4 = (const float4*)src + (size_t)jj * 2;
        ((uint4*)g_wh)[j] = f32x8_to_h8(s4[0], s4[1]);
    }
    if (i < n_nodes * 2) g_denom[i] = 0.f;
}

// ---------------- fp16 wmma GEMM (8 warps, 64x32 warp tiles) ----------------
// mode 0: A = g_xh [M,128], grid.x = 4 covers 512 output cols, OUT = fp16:
//         bn<256 -> Wl/bl -> g_xlh col (bn&255);  bn>=256 -> Wr/br -> g_xrh
// mode 1: A = g_numer [M,256] normalized on stage (/denom + bias_conv) -> fp16,
//         W = Wo half, bias = biasa (=bo), OUT = fp32 Cparam [M,128]
#define BM 128
#define BN 128
#define BK 32
#define BKP 40          // padded smem stride in halves

__global__ __launch_bounds__(256, 2) void gemm_f16(
    const float* __restrict__ biasa, const float* __restrict__ biasb,
    const float* __restrict__ bias_conv,
    float* __restrict__ Cparam, int mode, int M, int K)
{
    __shared__ __half As[BM][BKP];
    __shared__ __half Bs[BM][BKP];

    int tid  = threadIdx.x;
    int wid  = tid >> 5;
    int lane = tid & 31;
    int bm = blockIdx.y * BM;
    int bn = blockIdx.x * BN;

    const __half* Wh;
    const float*  bias;
    __half* Ch = nullptr;
    float*  Cf = nullptr;
    int cbase;
    if (mode == 0) {
        bool second = bn >= 256;
        int wrow = bn & 255;
        Wh   = g_wh + (second ? (HD * D_DIM) : 0) + (size_t)wrow * K;
        bias = (second ? biasb : biasa) + wrow;
        Ch   = second ? g_xrh : g_xlh;
        cbase = wrow;
    } else {
        Wh   = g_wh + 2 * HD * D_DIM;
        bias = biasa;
        Cf = Cparam; cbase = 0;
    }

    // warp tiling: 2 warps along M (64 rows), 4 along N (32 cols)
    int wm = (wid & 1) * 64;
    int wn = (wid >> 1) * 32;

    // ---- bias -> accumulator init ----
    float* bias_s = (float*)&As[0][0];
    for (int i = tid; i < 16 * BN; i += 256) bias_s[i] = bias[i & 127];
    __syncthreads();

    wmma::fragment<wmma::accumulator, 16, 16, 16, float> acc[4][2];
#pragma unroll
    for (int i = 0; i < 4; i++)
#pragma unroll
        for (int j = 0; j < 2; j++)
            wmma::load_matrix_sync(acc[i][j], bias_s + wn + j * 16, BN, wmma::mem_row_major);
    __syncthreads();

    for (int k0 = 0; k0 < K; k0 += BK) {
        int head = (k0 >= D_DIM) ? 1 : 0;       // used only in mode 1 (K=256)
#pragma unroll
        for (int it = 0; it < 2; it++) {
            int idx = tid + it * 256;
            int row = idx >> 2;
            int q   = idx & 3;
            int grow = bm + row;
            uint4 u = make_uint4(0u, 0u, 0u, 0u);
            if (grow < M) {
                if (mode == 0) {
                    u = *(const uint4*)(g_xh + (size_t)grow * K + k0 + q * 8);
                } else {
                    const float* ap = g_numer + (size_t)grow * K + k0 + q * 8;
                    float4 a = *(const float4*)(ap);
                    float4 b = *(const float4*)(ap + 4);
                    float inv = 1.0f / (g_denom[(size_t)grow * 2 + head] + 1e-16f);
                    const float* bc = bias_conv + k0 + q * 8;
                    float4 c0 = *(const float4*)(bc);
                    float4 c1 = *(const float4*)(bc + 4);
                    a.x = a.x * inv + c0.x; a.y = a.y * inv + c0.y;
                    a.z = a.z * inv + c0.z; a.w = a.w * inv + c0.w;
                    b.x = b.x * inv + c1.x; b.y = b.y * inv + c1.y;
                    b.z = b.z * inv + c1.z; b.w = b.w * inv + c1.w;
                    u = f32x8_to_h8(a, b);
                }
            }
            *(uint4*)&As[row][q * 8] = u;
            uint4 w = *(const uint4*)(Wh + (size_t)row * K + k0 + q * 8);
            *(uint4*)&Bs[row][q * 8] = w;
        }
        __syncthreads();

#pragma unroll
        for (int kk = 0; kk < BK; kk += 16) {
            wmma::fragment<wmma::matrix_a, 16, 16, 16, __half, wmma::row_major> af[4];
            wmma::fragment<wmma::matrix_b, 16, 16, 16, __half, wmma::col_major> bf[2];
#pragma unroll
            for (int i = 0; i < 4; i++)
                wmma::load_matrix_sync(af[i], &As[wm + i * 16][kk], BKP);
#pragma unroll
            for (int j = 0; j < 2; j++)
                wmma::load_matrix_sync(bf[j], &Bs[wn + j * 16][kk], BKP);
#pragma unroll
            for (int i = 0; i < 4; i++)
#pragma unroll
                for (int j = 0; j < 2; j++)
                    wmma::mma_sync(acc[i][j], af[i], bf[j], acc[i][j]);
        }
        __syncthreads();
    }

    // epilogue
    if (mode == 1 && bm + BM <= M) {
#pragma unroll
        for (int i = 0; i < 4; i++)
#pragma unroll
            for (int j = 0; j < 2; j++)
                wmma::store_matrix_sync(Cf + (size_t)(bm + wm + i * 16) * D_DIM + wn + j * 16,
                                        acc[i][j], D_DIM, wmma::mem_row_major);
    } else {
        // staged epilogue (fp16 output for mode 0; guarded fp32 for mode-1 remainder)
        float* sw = (float*)&As[0][0] + wid * (16 * 20);   // 8 warps x 1280B = 10KB < 20KB
        int r  = lane >> 1;
        int c0 = (lane & 1) * 8;
#pragma unroll
        for (int i = 0; i < 4; i++)
#pragma unroll
            for (int j = 0; j < 2; j++) {
                wmma::store_matrix_sync(sw, acc[i][j], 20, wmma::mem_row_major);
                __syncwarp();
                int grow = bm + wm + i * 16 + r;
                if (grow < M) {
                    const float* s = sw + r * 20 + c0;
                    if (mode == 0) {
                        float4 f0 = make_float4(s[0], s[1], s[2], s[3]);
                        float4 f1 = make_float4(s[4], s[5], s[6], s[7]);
                        *(uint4*)(Ch + (size_t)grow * HD + cbase + wn + j * 16 + c0)
                            = f32x8_to_h8(f0, f1);
                    } else {
                        float* dst = Cf + (size_t)grow * D_DIM + wn + j * 16 + c0;
#pragma unroll
                        for (int c = 0; c < 8; c++) dst[c] = s[c];
                    }
                }
                __syncwarp();
            }
    }
}

// ---------------- fused edge pass: both heads per warp, 2 edges per warp ----------------
// xl/xr rows are fp16: 256 halves = 512B = 32 lanes x uint4. Lanes 0-15 = head 0,
// lanes 16-31 = head 1 (global half index = lane*8). Segmented reduce at width 16.
// Working set xlh+xrh+numer ~ 102MB -> L2-resident.
__global__ __launch_bounds__(256) void edge_fused_kernel(
    const int* __restrict__ ei, const float* __restrict__ att,
    int E, int n_nodes)
{
    int gw = (blockIdx.x * blockDim.x + threadIdx.x) >> 5;
    int lane = threadIdx.x & 31;
    int ET = E + n_nodes;
    int e0 = gw * 2, e1 = gw * 2 + 1;
    if (e0 >= ET) return;

    int s0, d0;
    if (e0 < E) { s0 = ei[e0]; d0 = ei[(size_t)E + e0]; }
    else        { s0 = d0 = e0 - E; }
    bool v0 = (unsigned)s0 < (unsigned)n_nodes && (unsigned)d0 < (unsigned)n_nodes;

    int s1 = 0, d1 = 0;
    bool v1 = e1 < ET;
    if (v1) {
        if (e1 < E) { s1 = ei[e1]; d1 = ei[(size_t)E + e1]; }
        else        { s1 = d1 = e1 - E; }
        v1 = (unsigned)s1 < (unsigned)n_nodes && (unsigned)d1 < (unsigned)n_nodes;
    }

    // per-lane attention slice: att[lane*8 .. lane*8+8)
    float atv[8];
    {
        const float4* ap = (const float4*)(att) + lane * 2;
        float4 a0 = ap[0], a1 = ap[1];
        atv[0] = a0.x; atv[1] = a0.y; atv[2] = a0.z; atv[3] = a0.w;
        atv[4] = a1.x; atv[5] = a1.y; atv[6] = a1.z; atv[7] = a1.w;
    }

    uint4 ua0 = make_uint4(0,0,0,0), ub0 = ua0, ua1 = ua0, ub1 = ua0;
    if (v0) {
        ua0 = ((const uint4*)g_xlh)[(size_t)s0 * 32 + lane];
        ub0 = ((const uint4*)g_xrh)[(size_t)d0 * 32 + lane];
    }
    if (v1) {
        ua1 = ((const uint4*)g_xlh)[(size_t)s1 * 32 + lane];
        ub1 = ((const uint4*)g_xrh)[(size_t)d1 * 32 + lane];
    }

    float xa0[8], xb0[8], xa1[8], xb1[8];
    h8_to_f8(ua0, xa0); h8_to_f8(ub0, xb0);
    h8_to_f8(ua1, xa1); h8_to_f8(ub1, xb1);

    float dot0 = 0.f, dot1 = 0.f;
#pragma unroll
    for (int k = 0; k < 8; k++) {
        float e = xa0[k] + xb0[k];
        e = e > 0.f ? e : NEG_SLOPE * e;
        dot0 += e * atv[k];
        float f = xa1[k] + xb1[k];
        f = f > 0.f ? f : NEG_SLOPE * f;
        dot1 += f * atv[k];
    }
    // segmented reduce over each 16-lane half (head)
#pragma unroll
    for (int o = 8; o > 0; o >>= 1) {
        dot0 += __shfl_xor_sync(0xffffffffu, dot0, o);
        dot1 += __shfl_xor_sync(0xffffffffu, dot1, o);
    }
    float p0 = __expf(dot0);   // lanes 0-15: head0 p; lanes 16-31: head1 p
    float p1 = __expf(dot1);

    if ((lane == 0 || lane == 16) && v0) atomicAdd(&g_denom[(size_t)d0 * 2 + (lane >> 4)], p0);
    if ((lane == 1 || lane == 17) && v1) atomicAdd(&g_denom[(size_t)d1 * 2 + (lane >> 4)], p1);

    if (v0) {
        float* np = g_numer + (size_t)d0 * HD + lane * 8;
        red_add_v4(np,     xa0[0] * p0, xa0[1] * p0, xa0[2] * p0, xa0[3] * p0);
        red_add_v4(np + 4, xa0[4] * p0, xa0[5] * p0, xa0[6] * p0, xa0[7] * p0);
    }
    if (v1) {
        float* np = g_numer + (size_t)d1 * HD + lane * 8;
        red_add_v4(np,     xa1[0] * p1, xa1[1] * p1, xa1[2] * p1, xa1[3] * p1);
        red_add_v4(np + 4, xa1[4] * p1, xa1[5] * p1, xa1[6] * p1, xa1[7] * p1);
    }
}

// ---------------- launch ----------------
extern "C" void kernel_launch(void* const* d_in, const int* in_sizes, int n_in,
                              void* d_out, int out_size)
{
    const float* x         = (const float*)d_in[0];
    const int*   ei        = (const int*)d_in[1];     // int32 (JAX x64-disabled)
    const float* Wl        = (const float*)d_in[2];
    const float* bl        = (const float*)d_in[3];
    const float* Wr        = (const float*)d_in[4];
    const float* br        = (const float*)d_in[5];
    const float* att       = (const float*)d_in[6];
    const float* bias_conv = (const float*)d_in[7];
    const float* Wo        = (const float*)d_in[8];
    const float* bo        = (const float*)d_in[9];

    int N = in_sizes[0] / D_DIM;
    int E = in_sizes[1] / 2;
    int ET = E + N;
    int mtiles = (N + BM - 1) / BM;

    // init: zero numer/denom + convert x and weights to fp16
    {
        int t = N * 80 + 12288;
        init_kernel<<<(t + 255) / 256, 256>>>(x, Wl, Wr, Wo, N);
    }
    // fused projections (fp16 out): xlh = x@Wl^T+bl, xrh = x@Wr^T+br
    {
        dim3 grid(4, mtiles);
        gemm_f16<<<grid, 256>>>(bl, br, nullptr, nullptr, 0, N, D_DIM);
    }
    // fused edge pass: both heads per warp, 2 edges per warp
    {
        int warps = (ET + 1) / 2;
        int blocks = (warps + 7) / 8;
        edge_fused_kernel<<<blocks, 256>>>(ei, att, E, N);
    }
    // final projection with fused normalize: out = (numer/denom + bias_conv)@Wo^T + bo
    {
        dim3 grid(1, mtiles);
        gemm_f16<<<grid, 256>>>(bo, nullptr, bias_conv, (float*)d_out, 1, N, HD);
    }
}

// round 16
// speedup vs baseline: 1.0144x; 1.0144x over previous
#include <cuda_runtime.h>
#include <cuda_bf16.h>
#include <cuda_fp16.h>
#include <mma.h>
#include <cstdint>

using namespace nvcuda;

// Problem constants (fixed by the dataset)
#define MAXN 50000
#define MAXE 400000
#define HD 256          // H * D
#define D_DIM 128
#define NEG_SLOPE 0.2f

// ---------------- scratch (no allocations allowed) ----------------
__device__ __half g_xlh[(size_t)MAXN * HD];     // source projection, fp16
__device__ __half g_xrh[(size_t)MAXN * HD];     // target projection, fp16
__device__ float  g_numer[(size_t)MAXN * HD];   // weighted sums (fp32 accumulate)
__device__ float  g_denom[(size_t)MAXN * 2];    // sum of exp(score) per node/head
__device__ __half g_xh[(size_t)MAXN * D_DIM];   // x in fp16
__device__ __half g_wh[3 * HD * D_DIM];         // Wl, Wr, Wo in fp16

__device__ __forceinline__ void red_add_v4(float* p, float a, float b, float c, float d) {
    asm volatile("red.global.add.v4.f32 [%0], {%1,%2,%3,%4};"
                 :: "l"(p), "f"(a), "f"(b), "f"(c), "f"(d) : "memory");
}
__device__ __forceinline__ uint4 f32x8_to_h8(float4 a, float4 b) {
    __half2 h0 = __floats2half2_rn(a.x, a.y);
    __half2 h1 = __floats2half2_rn(a.z, a.w);
    __half2 h2 = __floats2half2_rn(b.x, b.y);
    __half2 h3 = __floats2half2_rn(b.z, b.w);
    uint4 u;
    u.x = *(uint32_t*)&h0; u.y = *(uint32_t*)&h1;
    u.z = *(uint32_t*)&h2; u.w = *(uint32_t*)&h3;
    return u;
}
__device__ __forceinline__ void h8_to_f8(uint4 u, float* f) {
    float2 t;
    t = __half22float2(*(__half2*)&u.x); f[0] = t.x; f[1] = t.y;
    t = __half22float2(*(__half2*)&u.y); f[2] = t.x; f[3] = t.y;
    t = __half22float2(*(__half2*)&u.z); f[4] = t.x; f[5] = t.y;
    t = __half22float2(*(__half2*)&u.w); f[6] = t.x; f[7] = t.y;
}

// ---------------- init: zero numer/denom + convert x, Wl, Wr, Wo to fp16 ----------------
__global__ void init_kernel(const float* __restrict__ x,
                            const float* __restrict__ Wl,
                            const float* __restrict__ Wr,
                            const float* __restrict__ Wo, int n_nodes) {
    int i = blockIdx.x * blockDim.x + threadIdx.x;
    int t0 = n_nodes * 64;
    int t1 = t0 + n_nodes * 16;
    if (i < t0) {
        ((float4*)g_numer)[i] = make_float4(0.f, 0.f, 0.f, 0.f);
    } else if (i < t1) {
        int j = i - t0;                       // 8-float chunk of x
        const float4* src = (const float4*)x + (size_t)j * 2;
        ((uint4*)g_xh)[j] = f32x8_to_h8(src[0], src[1]);
    } else if (i < t1 + 12288) {
        int j = i - t1;                       // 8-float chunk; 4096 chunks per matrix
        const float* src = (j < 4096) ? Wl : (j < 8192) ? Wr : Wo;
        int jj = j & 4095;
        const float4* s4 = (const float4*)src + (size_t)jj * 2;
        ((uint4*)g_wh)[j] = f32x8_to_h8(s4[0], s4[1]);
    }
    if (i < n_nodes * 2) g_denom[i] = 0.f;
}

#define BM 128
#define BN 128
#define BK 32
#define BKP 40          // padded smem stride in halves

// ---------------- projection GEMM (mode 0): x@{Wl,Wr}^T + bias -> fp16 xlh/xrh ----------------
// grid.x = 4: bn<256 -> Wl/bl -> g_xlh col (bn&255); bn>=256 -> Wr/br -> g_xrh
__global__ __launch_bounds__(256, 2) void gemm_proj(
    const float* __restrict__ biasa, const float* __restrict__ biasb, int M)
{
    const int K = D_DIM;
    __shared__ __half As[BM][BKP];
    __shared__ __half Bs[BM][BKP];

    int tid  = threadIdx.x;
    int wid  = tid >> 5;
    int lane = tid & 31;
    int bm = blockIdx.y * BM;
    int bn = blockIdx.x * BN;

    bool second = bn >= 256;
    int wrow = bn & 255;
    const __half* Wh = g_wh + (second ? (HD * D_DIM) : 0) + (size_t)wrow * K;
    const float* bias = (second ? biasb : biasa) + wrow;
    __half* Ch = second ? g_xrh : g_xlh;
    int cbase = wrow;

    int wm = (wid & 1) * 64;
    int wn = (wid >> 1) * 32;

    float* bias_s = (float*)&As[0][0];
    for (int i = tid; i < 16 * BN; i += 256) bias_s[i] = bias[i & 127];
    __syncthreads();

    wmma::fragment<wmma::accumulator, 16, 16, 16, float> acc[4][2];
#pragma unroll
    for (int i = 0; i < 4; i++)
#pragma unroll
        for (int j = 0; j < 2; j++)
            wmma::load_matrix_sync(acc[i][j], bias_s + wn + j * 16, BN, wmma::mem_row_major);
    __syncthreads();

    for (int k0 = 0; k0 < K; k0 += BK) {
#pragma unroll
        for (int it = 0; it < 2; it++) {
            int idx = tid + it * 256;
            int row = idx >> 2;
            int q   = idx & 3;
            int grow = bm + row;
            uint4 u = make_uint4(0u, 0u, 0u, 0u);
            if (grow < M) u = *(const uint4*)(g_xh + (size_t)grow * K + k0 + q * 8);
            *(uint4*)&As[row][q * 8] = u;
            uint4 w = *(const uint4*)(Wh + (size_t)row * K + k0 + q * 8);
            *(uint4*)&Bs[row][q * 8] = w;
        }
        __syncthreads();
#pragma unroll
        for (int kk = 0; kk < BK; kk += 16) {
            wmma::fragment<wmma::matrix_a, 16, 16, 16, __half, wmma::row_major> af[4];
            wmma::fragment<wmma::matrix_b, 16, 16, 16, __half, wmma::col_major> bf[2];
#pragma unroll
            for (int i = 0; i < 4; i++)
                wmma::load_matrix_sync(af[i], &As[wm + i * 16][kk], BKP);
#pragma unroll
            for (int j = 0; j < 2; j++)
                wmma::load_matrix_sync(bf[j], &Bs[wn + j * 16][kk], BKP);
#pragma unroll
            for (int i = 0; i < 4; i++)
#pragma unroll
                for (int j = 0; j < 2; j++)
                    wmma::mma_sync(acc[i][j], af[i], bf[j], acc[i][j]);
        }
        __syncthreads();
    }

    // fp16 epilogue: stage per-fragment, convert, 16B stores
    float* sw = (float*)&As[0][0] + wid * (16 * 20);   // 8 warps x 1280B = 10KB
    int r  = lane >> 1;
    int c0 = (lane & 1) * 8;
#pragma unroll
    for (int i = 0; i < 4; i++)
#pragma unroll
        for (int j = 0; j < 2; j++) {
            wmma::store_matrix_sync(sw, acc[i][j], 20, wmma::mem_row_major);
            __syncwarp();
            int grow = bm + wm + i * 16 + r;
            if (grow < M) {
                const float* s = sw + r * 20 + c0;
                float4 f0 = make_float4(s[0], s[1], s[2], s[3]);
                float4 f1 = make_float4(s[4], s[5], s[6], s[7]);
                *(uint4*)(Ch + (size_t)grow * HD + cbase + wn + j * 16 + c0) = f32x8_to_h8(f0, f1);
            }
            __syncwarp();
        }
}

// ---------------- output GEMM (mode 1): (numer/denom + bias_conv)@Wo^T + bo -> fp32 ----------------
__global__ __launch_bounds__(256, 2) void gemm_out(
    const float* __restrict__ bo, const float* __restrict__ bias_conv,
    float* __restrict__ C, int M)
{
    const int K = HD;
    __shared__ __half As[BM][BKP];
    __shared__ __half Bs[BM][BKP];

    int tid  = threadIdx.x;
    int wid  = tid >> 5;
    int lane = tid & 31;
    int bm = blockIdx.y * BM;

    const __half* Wh = g_wh + 2 * HD * D_DIM;

    int wm = (wid & 1) * 64;
    int wn = (wid >> 1) * 32;

    float* bias_s = (float*)&As[0][0];
    for (int i = tid; i < 16 * BN; i += 256) bias_s[i] = bo[i & 127];
    __syncthreads();

    wmma::fragment<wmma::accumulator, 16, 16, 16, float> acc[4][2];
#pragma unroll
    for (int i = 0; i < 4; i++)
#pragma unroll
        for (int j = 0; j < 2; j++)
            wmma::load_matrix_sync(acc[i][j], bias_s + wn + j * 16, BN, wmma::mem_row_major);
    __syncthreads();

    for (int k0 = 0; k0 < K; k0 += BK) {
        int head = (k0 >= D_DIM) ? 1 : 0;
#pragma unroll
        for (int it = 0; it < 2; it++) {
            int idx = tid + it * 256;
            int row = idx >> 2;
            int q   = idx & 3;
            int grow = bm + row;
            uint4 u = make_uint4(0u, 0u, 0u, 0u);
            if (grow < M) {
                float inv = 1.0f / (g_denom[(size_t)grow * 2 + head] + 1e-16f);
                const float* ap = g_numer + (size_t)grow * K + k0 + q * 8;
                const float* bc = bias_conv + k0 + q * 8;
                // 4 floats at a time to limit live registers
                float4 a = *(const float4*)(ap);
                float4 c0v = *(const float4*)(bc);
                a.x = a.x * inv + c0v.x; a.y = a.y * inv + c0v.y;
                a.z = a.z * inv + c0v.z; a.w = a.w * inv + c0v.w;
                __half2 h0 = __floats2half2_rn(a.x, a.y);
                __half2 h1 = __floats2half2_rn(a.z, a.w);
                float4 b = *(const float4*)(ap + 4);
                float4 c1v = *(const float4*)(bc + 4);
                b.x = b.x * inv + c1v.x; b.y = b.y * inv + c1v.y;
                b.z = b.z * inv + c1v.z; b.w = b.w * inv + c1v.w;
                __half2 h2 = __floats2half2_rn(b.x, b.y);
                __half2 h3 = __floats2half2_rn(b.z, b.w);
                u.x = *(uint32_t*)&h0; u.y = *(uint32_t*)&h1;
                u.z = *(uint32_t*)&h2; u.w = *(uint32_t*)&h3;
            }
            *(uint4*)&As[row][q * 8] = u;
            uint4 w = *(const uint4*)(Wh + (size_t)row * K + k0 + q * 8);
            *(uint4*)&Bs[row][q * 8] = w;
        }
        __syncthreads();
#pragma unroll
        for (int kk = 0; kk < BK; kk += 16) {
            wmma::fragment<wmma::matrix_a, 16, 16, 16, __half, wmma::row_major> af[4];
            wmma::fragment<wmma::matrix_b, 16, 16, 16, __half, wmma::col_major> bf[2];
#pragma unroll
            for (int i = 0; i < 4; i++)
                wmma::load_matrix_sync(af[i], &As[wm + i * 16][kk], BKP);
#pragma unroll
            for (int j = 0; j < 2; j++)
                wmma::load_matrix_sync(bf[j], &Bs[wn + j * 16][kk], BKP);
#pragma unroll
            for (int i = 0; i < 4; i++)
#pragma unroll
                for (int j = 0; j < 2; j++)
                    wmma::mma_sync(acc[i][j], af[i], bf[j], acc[i][j]);
        }
        __syncthreads();
    }

    if (bm + BM <= M) {
#pragma unroll
        for (int i = 0; i < 4; i++)
#pragma unroll
            for (int j = 0; j < 2; j++)
                wmma::store_matrix_sync(C + (size_t)(bm + wm + i * 16) * D_DIM + wn + j * 16,
                                        acc[i][j], D_DIM, wmma::mem_row_major);
    } else {
        float* sw = (float*)&As[0][0] + wid * (16 * 20);
        int r  = lane >> 1;
        int c0 = (lane & 1) * 8;
#pragma unroll
        for (int i = 0; i < 4; i++)
#pragma unroll
            for (int j = 0; j < 2; j++) {
                wmma::store_matrix_sync(sw, acc[i][j], 20, wmma::mem_row_major);
                __syncwarp();
                int grow = bm + wm + i * 16 + r;
                if (grow < M) {
                    float* dst = C + (size_t)grow * D_DIM + wn + j * 16 + c0;
                    const float* s = sw + r * 20 + c0;
#pragma unroll
                    for (int c = 0; c < 8; c++) dst[c] = s[c];
                }
                __syncwarp();
            }
    }
}

// ---------------- fused edge pass: both heads per warp, 2 edges per warp (R15, unchanged) ----------------
__global__ __launch_bounds__(256) void edge_fused_kernel(
    const int* __restrict__ ei, const float* __restrict__ att,
    int E, int n_nodes)
{
    int gw = (blockIdx.x * blockDim.x + threadIdx.x) >> 5;
    int lane = threadIdx.x & 31;
    int ET = E + n_nodes;
    int e0 = gw * 2, e1 = gw * 2 + 1;
    if (e0 >= ET) return;

    int s0, d0;
    if (e0 < E) { s0 = ei[e0]; d0 = ei[(size_t)E + e0]; }
    else        { s0 = d0 = e0 - E; }
    bool v0 = (unsigned)s0 < (unsigned)n_nodes && (unsigned)d0 < (unsigned)n_nodes;

    int s1 = 0, d1 = 0;
    bool v1 = e1 < ET;
    if (v1) {
        if (e1 < E) { s1 = ei[e1]; d1 = ei[(size_t)E + e1]; }
        else        { s1 = d1 = e1 - E; }
        v1 = (unsigned)s1 < (unsigned)n_nodes && (unsigned)d1 < (unsigned)n_nodes;
    }

    float atv[8];
    {
        const float4* ap = (const float4*)(att) + lane * 2;
        float4 a0 = ap[0], a1 = ap[1];
        atv[0] = a0.x; atv[1] = a0.y; atv[2] = a0.z; atv[3] = a0.w;
        atv[4] = a1.x; atv[5] = a1.y; atv[6] = a1.z; atv[7] = a1.w;
    }

    uint4 ua0 = make_uint4(0,0,0,0), ub0 = ua0, ua1 = ua0, ub1 = ua0;
    if (v0) {
        ua0 = ((const uint4*)g_xlh)[(size_t)s0 * 32 + lane];
        ub0 = ((const uint4*)g_xrh)[(size_t)d0 * 32 + lane];
    }
    if (v1) {
        ua1 = ((const uint4*)g_xlh)[(size_t)s1 * 32 + lane];
        ub1 = ((const uint4*)g_xrh)[(size_t)d1 * 32 + lane];
    }

    float xa0[8], xb0[8], xa1[8], xb1[8];
    h8_to_f8(ua0, xa0); h8_to_f8(ub0, xb0);
    h8_to_f8(ua1, xa1); h8_to_f8(ub1, xb1);

    float dot0 = 0.f, dot1 = 0.f;
#pragma unroll
    for (int k = 0; k < 8; k++) {
        float e = xa0[k] + xb0[k];
        e = e > 0.f ? e : NEG_SLOPE * e;
        dot0 += e * atv[k];
        float f = xa1[k] + xb1[k];
        f = f > 0.f ? f : NEG_SLOPE * f;
        dot1 += f * atv[k];
    }
#pragma unroll
    for (int o = 8; o > 0; o >>= 1) {
        dot0 += __shfl_xor_sync(0xffffffffu, dot0, o);
        dot1 += __shfl_xor_sync(0xffffffffu, dot1, o);
    }
    float p0 = __expf(dot0);
    float p1 = __expf(dot1);

    if ((lane == 0 || lane == 16) && v0) atomicAdd(&g_denom[(size_t)d0 * 2 + (lane >> 4)], p0);
    if ((lane == 1 || lane == 17) && v1) atomicAdd(&g_denom[(size_t)d1 * 2 + (lane >> 4)], p1);

    if (v0) {
        float* np = g_numer + (size_t)d0 * HD + lane * 8;
        red_add_v4(np,     xa0[0] * p0, xa0[1] * p0, xa0[2] * p0, xa0[3] * p0);
        red_add_v4(np + 4, xa0[4] * p0, xa0[5] * p0, xa0[6] * p0, xa0[7] * p0);
    }
    if (v1) {
        float* np = g_numer + (size_t)d1 * HD + lane * 8;
        red_add_v4(np,     xa1[0] * p1, xa1[1] * p1, xa1[2] * p1, xa1[3] * p1);
        red_add_v4(np + 4, xa1[4] * p1, xa1[5] * p1, xa1[6] * p1, xa1[7] * p1);
    }
}

// ---------------- launch ----------------
extern "C" void kernel_launch(void* const* d_in, const int* in_sizes, int n_in,
                              void* d_out, int out_size)
{
    const float* x         = (const float*)d_in[0];
    const int*   ei        = (const int*)d_in[1];     // int32 (JAX x64-disabled)
    const float* Wl        = (const float*)d_in[2];
    const float* bl        = (const float*)d_in[3];
    const float* Wr        = (const float*)d_in[4];
    const float* br        = (const float*)d_in[5];
    const float* att       = (const float*)d_in[6];
    const float* bias_conv = (const float*)d_in[7];
    const float* Wo        = (const float*)d_in[8];
    const float* bo        = (const float*)d_in[9];

    int N = in_sizes[0] / D_DIM;
    int E = in_sizes[1] / 2;
    int ET = E + N;
    int mtiles = (N + BM - 1) / BM;

    // init: zero numer/denom + convert x and weights to fp16
    {
        int t = N * 80 + 12288;
        init_kernel<<<(t + 255) / 256, 256>>>(x, Wl, Wr, Wo, N);
    }
    // fused projections (fp16 out): xlh = x@Wl^T+bl, xrh = x@Wr^T+br
    {
        dim3 grid(4, mtiles);
        gemm_proj<<<grid, 256>>>(bl, br, N);
    }
    // fused edge pass: both heads per warp, 2 edges per warp
    {
        int warps = (ET + 1) / 2;
        int blocks = (warps + 7) / 8;
        edge_fused_kernel<<<blocks, 256>>>(ei, att, E, N);
    }
    // final projection with fused normalize: out = (numer/denom + bias_conv)@Wo^T + bo
    {
        dim3 grid(1, mtiles);
        gemm_out<<<grid, 256>>>(bo, bias_conv, (float*)d_out, N);
    }
}

// round 17
// speedup vs baseline: 1.0565x; 1.0415x over previous
#include <cuda_runtime.h>
#include <cuda_bf16.h>
#include <cuda_fp16.h>
#include <mma.h>
#include <cstdint>

using namespace nvcuda;

// Problem constants (fixed by the dataset)
#define MAXN 50000
#define MAXE 400000
#define HD 256          // H * D
#define D_DIM 128
#define NEG_SLOPE 0.2f

// ---------------- scratch (no allocations allowed) ----------------
__device__ __half g_xlh[(size_t)MAXN * HD];     // source projection fp16; reused as feat
__device__ __half g_xrh[(size_t)MAXN * HD];     // target projection, fp16
__device__ float  g_numer[(size_t)MAXN * HD];   // weighted sums (fp32 accumulate)
__device__ float  g_denom[(size_t)MAXN * 2];    // sum of exp(score) per node/head
__device__ __half g_xh[(size_t)MAXN * D_DIM];   // x in fp16
__device__ __half g_wh[3 * HD * D_DIM];         // Wl, Wr, Wo in fp16

__device__ __forceinline__ void red_add_v4(float* p, float a, float b, float c, float d) {
    asm volatile("red.global.add.v4.f32 [%0], {%1,%2,%3,%4};"
                 :: "l"(p), "f"(a), "f"(b), "f"(c), "f"(d) : "memory");
}
__device__ __forceinline__ void cp_async16(uint32_t saddr, const void* g, int szok) {
    asm volatile("cp.async.ca.shared.global [%0], [%1], 16, %2;"
                 :: "r"(saddr), "l"(g), "r"(szok) : "memory");
}
__device__ __forceinline__ uint4 f32x8_to_h8(float4 a, float4 b) {
    __half2 h0 = __floats2half2_rn(a.x, a.y);
    __half2 h1 = __floats2half2_rn(a.z, a.w);
    __half2 h2 = __floats2half2_rn(b.x, b.y);
    __half2 h3 = __floats2half2_rn(b.z, b.w);
    uint4 u;
    u.x = *(uint32_t*)&h0; u.y = *(uint32_t*)&h1;
    u.z = *(uint32_t*)&h2; u.w = *(uint32_t*)&h3;
    return u;
}
__device__ __forceinline__ void h8_to_f8(uint4 u, float* f) {
    float2 t;
    t = __half22float2(*(__half2*)&u.x); f[0] = t.x; f[1] = t.y;
    t = __half22float2(*(__half2*)&u.y); f[2] = t.x; f[3] = t.y;
    t = __half22float2(*(__half2*)&u.z); f[4] = t.x; f[5] = t.y;
    t = __half22float2(*(__half2*)&u.w); f[6] = t.x; f[7] = t.y;
}

// ---------------- init: zero numer/denom + convert x, Wl, Wr, Wo to fp16 ----------------
__global__ void init_kernel(const float* __restrict__ x,
                            const float* __restrict__ Wl,
                            const float* __restrict__ Wr,
                            const float* __restrict__ Wo, int n_nodes) {
    int i = blockIdx.x * blockDim.x + threadIdx.x;
    int t0 = n_nodes * 64;
    int t1 = t0 + n_nodes * 16;
    if (i < t0) {
        ((float4*)g_numer)[i] = make_float4(0.f, 0.f, 0.f, 0.f);
    } else if (i < t1) {
        int j = i - t0;                       // 8-float chunk of x
        const float4* src = (const float4*)x + (size_t)j * 2;
        ((uint4*)g_xh)[j] = f32x8_to_h8(src[0], src[1]);
    } else if (i < t1 + 12288) {
        int j = i - t1;                       // 8-float chunk; 4096 chunks per matrix
        const float* src = (j < 4096) ? Wl : (j < 8192) ? Wr : Wo;
        int jj = j & 4095;
        const float4* s4 = (const float4*)src + (size_t)jj * 2;
        ((uint4*)g_wh)[j] = f32x8_to_h8(s4[0], s4[1]);
    }
    if (i < n_nodes * 2) g_denom[i] = 0.f;
}

// ---------------- normalize: feat = (numer/denom + bias_conv) -> fp16 into g_xlh ----------------
__global__ void normalize_kernel(const float* __restrict__ bias_conv, int n_nodes) {
    int i = blockIdx.x * blockDim.x + threadIdx.x;   // over n_nodes*32 8-float chunks
    if (i >= n_nodes * 32) return;
    int row = i >> 5;
    int q   = i & 31;                                // chunk within 256-col row
    int head = q >> 4;
    float inv = 1.0f / (g_denom[(size_t)row * 2 + head] + 1e-16f);
    const float* np = g_numer + (size_t)row * HD + q * 8;
    const float* bc = bias_conv + q * 8;
    float4 a = *(const float4*)np;
    float4 b = *(const float4*)(np + 4);
    float4 c0 = *(const float4*)bc;
    float4 c1 = *(const float4*)(bc + 4);
    a.x = a.x * inv + c0.x; a.y = a.y * inv + c0.y;
    a.z = a.z * inv + c0.z; a.w = a.w * inv + c0.w;
    b.x = b.x * inv + c1.x; b.y = b.y * inv + c1.y;
    b.z = b.z * inv + c1.z; b.w = b.w * inv + c1.w;
    ((uint4*)g_xlh)[i] = f32x8_to_h8(a, b);
}

#define BM 128
#define BN 128
#define BK 32
#define BKP 40          // padded smem stride in halves (80B rows, 16B aligned)

// ---------------- fp16 wmma GEMM, cp.async 2-stage (shared mainloop) ----------------
// mode 0 (proj): A = g_xh [M,128], grid.x = 4 -> {Wl/bl -> g_xlh, Wr/br -> g_xrh}, fp16 out
// mode 1 (out):  A = g_xlh-as-feat [M,256], W = Wo, bias = biasa (=bo), fp32 out Cparam
__global__ __launch_bounds__(256, 2) void gemm_f16p(
    const float* __restrict__ biasa, const float* __restrict__ biasb,
    float* __restrict__ Cparam, int mode, int M)
{
    __shared__ __half As[2][BM][BKP];
    __shared__ __half Bs[2][BM][BKP];

    int tid  = threadIdx.x;
    int wid  = tid >> 5;
    int lane = tid & 31;
    int bm = blockIdx.y * BM;
    int bn = blockIdx.x * BN;

    const __half* A;
    const __half* Wh;
    const float*  bias;
    __half* Ch = nullptr;
    float*  Cf = nullptr;
    int cbase = 0, K;
    if (mode == 0) {
        K = D_DIM;
        A = g_xh;
        bool second = bn >= 256;
        int wrow = bn & 255;
        Wh   = g_wh + (second ? (HD * D_DIM) : 0) + (size_t)wrow * K;
        bias = (second ? biasb : biasa) + wrow;
        Ch   = second ? g_xrh : g_xlh;
        cbase = wrow;
    } else {
        K = HD;
        A = g_xlh;                 // normalized feat, fp16
        Wh   = g_wh + 2 * HD * D_DIM;
        bias = biasa;
        Cf = Cparam;
    }

    int wm = (wid & 1) * 64;
    int wn = (wid >> 1) * 32;

    // ---- bias -> accumulator init (overlay in As[0]) ----
    float* bias_s = (float*)&As[0][0][0];     // 8KB < 10.2KB
    for (int i = tid; i < 16 * BN; i += 256) bias_s[i] = bias[i & 127];
    __syncthreads();

    wmma::fragment<wmma::accumulator, 16, 16, 16, float> acc[4][2];
#pragma unroll
    for (int i = 0; i < 4; i++)
#pragma unroll
        for (int j = 0; j < 2; j++)
            wmma::load_matrix_sync(acc[i][j], bias_s + wn + j * 16, BN, wmma::mem_row_major);
    __syncthreads();

    uint32_t as_base = (uint32_t)__cvta_generic_to_shared(&As[0][0][0]);
    uint32_t bs_base = (uint32_t)__cvta_generic_to_shared(&Bs[0][0][0]);

    auto load_tile = [&](int buf, int k0) {
#pragma unroll
        for (int it = 0; it < 2; it++) {
            int idx = tid + it * 256;          // 0..511
            int row = idx >> 2;
            int q   = idx & 3;                 // 8-half slot
            int grow = bm + row;
            uint32_t soff = (uint32_t)(buf * BM + row) * (BKP * 2) + q * 16;
            const __half* asrc = A + (size_t)(grow < M ? grow : 0) * K + k0 + q * 8;
            cp_async16(as_base + soff, asrc, grow < M ? 16 : 0);
            const __half* wsrc = Wh + (size_t)row * K + k0 + q * 8;
            cp_async16(bs_base + soff, wsrc, 16);
        }
    };

    int T = K / BK;
    load_tile(0, 0);
    asm volatile("cp.async.commit_group;");

    for (int t = 0; t < T; t++) {
        int buf = t & 1;
        if (t + 1 < T) {
            load_tile(buf ^ 1, (t + 1) * BK);
            asm volatile("cp.async.commit_group;");
            asm volatile("cp.async.wait_group 1;");
        } else {
            asm volatile("cp.async.wait_group 0;");
        }
        __syncthreads();

#pragma unroll
        for (int kk = 0; kk < BK; kk += 16) {
            wmma::fragment<wmma::matrix_a, 16, 16, 16, __half, wmma::row_major> af[4];
            wmma::fragment<wmma::matrix_b, 16, 16, 16, __half, wmma::col_major> bf[2];
#pragma unroll
            for (int i = 0; i < 4; i++)
                wmma::load_matrix_sync(af[i], &As[buf][wm + i * 16][kk], BKP);
#pragma unroll
            for (int j = 0; j < 2; j++)
                wmma::load_matrix_sync(bf[j], &Bs[buf][wn + j * 16][kk], BKP);
#pragma unroll
            for (int i = 0; i < 4; i++)
#pragma unroll
                for (int j = 0; j < 2; j++)
                    wmma::mma_sync(acc[i][j], af[i], bf[j], acc[i][j]);
        }
        __syncthreads();
    }

    // epilogue
    if (mode == 1 && bm + BM <= M) {
#pragma unroll
        for (int i = 0; i < 4; i++)
#pragma unroll
            for (int j = 0; j < 2; j++)
                wmma::store_matrix_sync(Cf + (size_t)(bm + wm + i * 16) * D_DIM + wn + j * 16,
                                        acc[i][j], D_DIM, wmma::mem_row_major);
    } else {
        float* sw = (float*)&As[0][0][0] + wid * (16 * 20);   // 8 x 1280B = 10KB
        int r  = lane >> 1;
        int c0 = (lane & 1) * 8;
#pragma unroll
        for (int i = 0; i < 4; i++)
#pragma unroll
            for (int j = 0; j < 2; j++) {
                wmma::store_matrix_sync(sw, acc[i][j], 20, wmma::mem_row_major);
                __syncwarp();
                int grow = bm + wm + i * 16 + r;
                if (grow < M) {
                    const float* s = sw + r * 20 + c0;
                    if (mode == 0) {
                        float4 f0 = make_float4(s[0], s[1], s[2], s[3]);
                        float4 f1 = make_float4(s[4], s[5], s[6], s[7]);
                        *(uint4*)(Ch + (size_t)grow * HD + cbase + wn + j * 16 + c0)
                            = f32x8_to_h8(f0, f1);
                    } else {
                        float* dst = Cf + (size_t)grow * D_DIM + wn + j * 16 + c0;
#pragma unroll
                        for (int c = 0; c < 8; c++) dst[c] = s[c];
                    }
                }
                __syncwarp();
            }
    }
}

// ---------------- fused edge pass: both heads per warp, 2 edges per warp (unchanged) ----------------
__global__ __launch_bounds__(256) void edge_fused_kernel(
    const int* __restrict__ ei, const float* __restrict__ att,
    int E, int n_nodes)
{
    int gw = (blockIdx.x * blockDim.x + threadIdx.x) >> 5;
    int lane = threadIdx.x & 31;
    int ET = E + n_nodes;
    int e0 = gw * 2, e1 = gw * 2 + 1;
    if (e0 >= ET) return;

    int s0, d0;
    if (e0 < E) { s0 = ei[e0]; d0 = ei[(size_t)E + e0]; }
    else        { s0 = d0 = e0 - E; }
    bool v0 = (unsigned)s0 < (unsigned)n_nodes && (unsigned)d0 < (unsigned)n_nodes;

    int s1 = 0, d1 = 0;
    bool v1 = e1 < ET;
    if (v1) {
        if (e1 < E) { s1 = ei[e1]; d1 = ei[(size_t)E + e1]; }
        else        { s1 = d1 = e1 - E; }
        v1 = (unsigned)s1 < (unsigned)n_nodes && (unsigned)d1 < (unsigned)n_nodes;
    }

    float atv[8];
    {
        const float4* ap = (const float4*)(att) + lane * 2;
        float4 a0 = ap[0], a1 = ap[1];
        atv[0] = a0.x; atv[1] = a0.y; atv[2] = a0.z; atv[3] = a0.w;
        atv[4] = a1.x; atv[5] = a1.y; atv[6] = a1.z; atv[7] = a1.w;
    }

    uint4 ua0 = make_uint4(0,0,0,0), ub0 = ua0, ua1 = ua0, ub1 = ua0;
    if (v0) {
        ua0 = ((const uint4*)g_xlh)[(size_t)s0 * 32 + lane];
        ub0 = ((const uint4*)g_xrh)[(size_t)d0 * 32 + lane];
    }
    if (v1) {
        ua1 = ((const uint4*)g_xlh)[(size_t)s1 * 32 + lane];
        ub1 = ((const uint4*)g_xrh)[(size_t)d1 * 32 + lane];
    }

    float xa0[8], xb0[8], xa1[8], xb1[8];
    h8_to_f8(ua0, xa0); h8_to_f8(ub0, xb0);
    h8_to_f8(ua1, xa1); h8_to_f8(ub1, xb1);

    float dot0 = 0.f, dot1 = 0.f;
#pragma unroll
    for (int k = 0; k < 8; k++) {
        float e = xa0[k] + xb0[k];
        e = e > 0.f ? e : NEG_SLOPE * e;
        dot0 += e * atv[k];
        float f = xa1[k] + xb1[k];
        f = f > 0.f ? f : NEG_SLOPE * f;
        dot1 += f * atv[k];
    }
#pragma unroll
    for (int o = 8; o > 0; o >>= 1) {
        dot0 += __shfl_xor_sync(0xffffffffu, dot0, o);
        dot1 += __shfl_xor_sync(0xffffffffu, dot1, o);
    }
    float p0 = __expf(dot0);
    float p1 = __expf(dot1);

    if ((lane == 0 || lane == 16) && v0) atomicAdd(&g_denom[(size_t)d0 * 2 + (lane >> 4)], p0);
    if ((lane == 1 || lane == 17) && v1) atomicAdd(&g_denom[(size_t)d1 * 2 + (lane >> 4)], p1);

    if (v0) {
        float* np = g_numer + (size_t)d0 * HD + lane * 8;
        red_add_v4(np,     xa0[0] * p0, xa0[1] * p0, xa0[2] * p0, xa0[3] * p0);
        red_add_v4(np + 4, xa0[4] * p0, xa0[5] * p0, xa0[6] * p0, xa0[7] * p0);
    }
    if (v1) {
        float* np = g_numer + (size_t)d1 * HD + lane * 8;
        red_add_v4(np,     xa1[0] * p1, xa1[1] * p1, xa1[2] * p1, xa1[3] * p1);
        red_add_v4(np + 4, xa1[4] * p1, xa1[5] * p1, xa1[6] * p1, xa1[7] * p1);
    }
}

// ---------------- launch ----------------
extern "C" void kernel_launch(void* const* d_in, const int* in_sizes, int n_in,
                              void* d_out, int out_size)
{
    const float* x         = (const float*)d_in[0];
    const int*   ei        = (const int*)d_in[1];     // int32 (JAX x64-disabled)
    const float* Wl        = (const float*)d_in[2];
    const float* bl        = (const float*)d_in[3];
    const float* Wr        = (const float*)d_in[4];
    const float* br        = (const float*)d_in[5];
    const float* att       = (const float*)d_in[6];
    const float* bias_conv = (const float*)d_in[7];
    const float* Wo        = (const float*)d_in[8];
    const float* bo        = (const float*)d_in[9];

    int N = in_sizes[0] / D_DIM;
    int E = in_sizes[1] / 2;
    int ET = E + N;
    int mtiles = (N + BM - 1) / BM;

    // init: zero numer/denom + convert x and weights to fp16
    {
        int t = N * 80 + 12288;
        init_kernel<<<(t + 255) / 256, 256>>>(x, Wl, Wr, Wo, N);
    }
    // fused projections (fp16 out): xlh = x@Wl^T+bl, xrh = x@Wr^T+br
    {
        dim3 grid(4, mtiles);
        gemm_f16p<<<grid, 256>>>(bl, br, nullptr, 0, N);
    }
    // fused edge pass: both heads per warp, 2 edges per warp
    {
        int warps = (ET + 1) / 2;
        int blocks = (warps + 7) / 8;
        edge_fused_kernel<<<blocks, 256>>>(ei, att, E, N);
    }
    // normalize feat (fp16 into g_xlh), then final projection
    {
        int t = N * 32;
        normalize_kernel<<<(t + 255) / 256, 256>>>(bias_conv, N);
        dim3 grid(1, mtiles);
        gemm_f16p<<<grid, 256>>>(bo, nullptr, (float*)d_out, 1, N);
    }
}